// round 11
// baseline (speedup 1.0000x reference)
#include <cuda_runtime.h>

// SeqSelfAttention (Bahdanau additive, windowed) — GB300 sm_103a
// B=4, L=1024, D=128, U=32, WIDTH=64, EPS=1e-7
//
// Algebra: window-max softmax shift only perturbs the +1e-7 denominator by
// exp(Mw-Mfull) (rel err <~1e-6); ba cancels exactly.
// R11: attn frozen at R10 (best measured; structure-invariant at ~10.6us).
// qk rebuilt: f32x2 packed FFMA (halved inst count), [d2][u] float4 W layout
// (conflict-free STS.128 staging, natural register pairs -> zero pack movs),
// 8 rows/warp (W reads amortized over 32 fma2).

#define LSEQ 1024
#define BB   4
#define DD   128
#define UU   32
#define TI   16
#define CW   80   // TI + 64
#define NROWS (BB*LSEQ)

typedef unsigned long long u64;

__device__ float g_q [NROWS*UU];
__device__ float g_kb[NROWS*UU];

__device__ __forceinline__ float fast_tanh(float x){
    float y; asm("tanh.approx.f32 %0, %1;" : "=f"(y) : "f"(x)); return y;
}
__device__ __forceinline__ void fma2(u64& d, u64 a, u64 b){
    asm("fma.rn.f32x2 %0, %1, %2, %0;" : "+l"(d) : "l"(a), "l"(b));
}
__device__ __forceinline__ void unpack2(u64 v, float& lo, float& hi){
    unsigned a, b;
    asm("mov.b64 {%0, %1}, %2;" : "=r"(a), "=r"(b) : "l"(v));
    lo = __uint_as_float(a); hi = __uint_as_float(b);
}

// ---------------------------------------------------------------------------
// Kernel 1: q = x @ Wt ; kb = x @ Wx + bh.  128 blocks x 128 thr,
// 32 rows/block, 8 rows/warp, f32x2 packed math.
// wtx[d2][u] = (Wt[2d2][u], Wt[2d2+1][u], Wx[2d2][u], Wx[2d2+1][u]).
// smem (dynamic): xs 16KB | wtx 32KB
// ---------------------------------------------------------------------------
#define QK_RPB 32
#define QK_SMEM_FLOATS (QK_RPB*DD + 64*32*4)   // 4096 + 8192 = 12288 (48KB)

extern __shared__ float smem[];

__global__ __launch_bounds__(128) void qk_kernel(
        const float* __restrict__ x,
        const float* __restrict__ Wt,
        const float* __restrict__ Wx,
        const float* __restrict__ bh)
{
    float* xs  = smem;                    // [32][128]
    float* wtx = smem + QK_RPB*DD;        // [64][32] float4 entries
    const int t    = threadIdx.x;
    const int row0 = blockIdx.x * QK_RPB;

    {   // stage xs (coalesced f4) and wtx (packed pairs, STS.128 c-free)
        const float4* xg = (const float4*)(x + row0*DD);
        float4* xs4 = (float4*)xs;
        #pragma unroll
        for (int i = 0; i < 8; i++) xs4[t + i*128] = xg[t + i*128];
        float4* wp = (float4*)wtx;
        #pragma unroll
        for (int i = 0; i < 16; i++){
            const int idx = t + i*128;          // [0,2048): d2 = idx>>5, u = idx&31
            const int d2 = idx >> 5, u = idx & 31;
            const int g0 = 64*d2 + u;           // (2*d2)*32 + u
            wp[idx] = make_float4(Wt[g0], Wt[g0+32], Wx[g0], Wx[g0+32]);
        }
    }
    __syncthreads();

    const int u  = t & 31;
    const int rg = t >> 5;
    const int rb = rg * 8;                 // 8 rows per warp
    u64 qa[8], ka[8];
    #pragma unroll
    for (int r = 0; r < 8; r++){ qa[r] = 0ull; ka[r] = 0ull; }

    const ulonglong2* wp2 = (const ulonglong2*)wtx;   // entry d2*32+u
    const ulonglong2* xs2 = (const ulonglong2*)xs;    // entry r*32+d4

    #pragma unroll 4
    for (int d4 = 0; d4 < 32; d4++){
        const ulonglong2 w0 = wp2[(2*d4  )*32 + u];   // conflict-free LDS.128
        const ulonglong2 w1 = wp2[(2*d4+1)*32 + u];
        #pragma unroll
        for (int r = 0; r < 8; r++){
            const ulonglong2 xr = xs2[(rb + r)*32 + d4];  // broadcast LDS.128
            fma2(qa[r], xr.x, w0.x);   // (x[4d4],x[4d4+1])·(Wt pair)
            fma2(ka[r], xr.x, w0.y);   //                 ·(Wx pair)
            fma2(qa[r], xr.y, w1.x);   // (x[4d4+2],x[4d4+3])
            fma2(ka[r], xr.y, w1.y);
        }
    }

    const float bhv = bh[u];
    #pragma unroll
    for (int r = 0; r < 8; r++){
        float lo, hi;
        unpack2(qa[r], lo, hi);
        g_q [(row0 + rb + r)*UU + u] = lo + hi;
        unpack2(ka[r], lo, hi);
        g_kb[(row0 + rb + r)*UU + u] = lo + hi + bhv;
    }
}

// ---------------------------------------------------------------------------
// Kernel 2: windowed attention (R10 verbatim — frozen best).
// grid (L/16, B) = 256 blocks, 256 thr. Warp w owns queries 2w, 2w+1;
// lane l batch-loads kb rows c0=2w+l, c1=c0+32 into registers (MLP 16),
// shared by both queries; q1 orphan row 2w+64 via u-parallel reduction.
// smem: xs[80][128] | kbs[80][36] | qs[16][32] | was[32] | Aw[8][132]
// ---------------------------------------------------------------------------
#define KBS  36
#define OFF_KBS  (CW*DD)                   // 10240
#define OFF_QS   (OFF_KBS + CW*KBS)        // 13120
#define OFF_WAS  (OFF_QS + TI*UU)          // 13632
#define OFF_AW   (OFF_WAS + UU)            // 13664
#define SMEM_FLOATS (OFF_AW + 8*132)       // 14720 floats = 58880 B

__global__ __launch_bounds__(256, 2) void attn_kernel(
        const float* __restrict__ x,
        const float* __restrict__ Wa,
        float* __restrict__ out)
{
    float* xs  = smem;
    float* kbs = smem + OFF_KBS;
    float* qs  = smem + OFF_QS;
    float* was = smem + OFF_WAS;
    float* Aw  = smem + OFF_AW;

    const int t    = threadIdx.x;
    const int i0   = blockIdx.x * TI;
    const int base = blockIdx.y * LSEQ;

    // ---- stage: xs[80][128] f4, kbs[80][36] f4, qs[16][32], was ----
    {
        float4* xs4 = (float4*)xs;
        const float4* xg4 = (const float4*)x;
        #pragma unroll
        for (int i = 0; i < 10; i++){
            const int idx = t + i*256;            // [0,2560) f4 of [80][32]
            const int c = idx >> 5, dq = idx & 31;
            const int j = i0 - 32 + c;
            float4 v = make_float4(0.f,0.f,0.f,0.f);
            if (j >= 0 && j < LSEQ) v = xg4[(base + j)*32 + dq];
            xs4[c*32 + dq] = v;
        }
        const float4* kg4 = (const float4*)g_kb;
        #pragma unroll
        for (int i = 0; i < 3; i++){
            const int idx = t + i*256;            // [0,640) f4 of [80][8]
            if (idx < 640){
                const int c = idx >> 3, u4 = idx & 7;
                const int j = i0 - 32 + c;
                float4 v = make_float4(0.f,0.f,0.f,0.f);
                if (j >= 0 && j < LSEQ) v = kg4[(base + j)*8 + u4];
                ((float4*)(kbs + c*KBS))[u4] = v;
            }
        }
        if (t < 128) ((float4*)qs)[t] = ((const float4*)(g_q + (base+i0)*UU))[t];
        if (t < 32) was[t] = Wa[t];
    }
    __syncthreads();

    const int w = t >> 5;
    const int l = t & 31;
    const int c0 = 2*w + l, c1 = c0 + 32;

    // ---- batch-load the lane's full kb working set (16 indep LDS.128) ----
    float4 kA[8], kB[8];
    {
        const float4* kAp = (const float4*)(kbs + c0*KBS);
        const float4* kBp = (const float4*)(kbs + c1*KBS);
        #pragma unroll
        for (int u4 = 0; u4 < 8; u4++) kA[u4] = kAp[u4];
        #pragma unroll
        for (int u4 = 0; u4 < 8; u4++) kB[u4] = kBp[u4];
    }

    // ---- logits: kA/kB in registers, shared by q0 and q1 ----
    float e0a = 0.f, e0b = 0.f, e1a = 0.f, e1b = 0.f;
    {
        const float4* q0p = (const float4*)(qs + 2*w*UU);
        const float4* q1p = q0p + 8;
        const float4* wap = (const float4*)was;
        #pragma unroll
        for (int u4 = 0; u4 < 8; u4++){
            const float4 wa = wap[u4];            // broadcast
            const float4 q0 = q0p[u4];            // broadcast
            const float4 q1 = q1p[u4];
            e0a += wa.x*fast_tanh(q0.x+kA[u4].x) + wa.y*fast_tanh(q0.y+kA[u4].y)
                 + wa.z*fast_tanh(q0.z+kA[u4].z) + wa.w*fast_tanh(q0.w+kA[u4].w);
            e0b += wa.x*fast_tanh(q0.x+kB[u4].x) + wa.y*fast_tanh(q0.y+kB[u4].y)
                 + wa.z*fast_tanh(q0.z+kB[u4].z) + wa.w*fast_tanh(q0.w+kB[u4].w);
            e1a += wa.x*fast_tanh(q1.x+kA[u4].x) + wa.y*fast_tanh(q1.y+kA[u4].y)
                 + wa.z*fast_tanh(q1.z+kA[u4].z) + wa.w*fast_tanh(q1.w+kA[u4].w);
            e1b += wa.x*fast_tanh(q1.x+kB[u4].x) + wa.y*fast_tanh(q1.y+kB[u4].y)
                 + wa.z*fast_tanh(q1.z+kB[u4].z) + wa.w*fast_tanh(q1.w+kB[u4].w);
        }
    }

    // ---- orphan row 2w+64 for q1: u-parallel (lane = unit) ----
    float eo;
    {
        const float pv = was[l] * fast_tanh(qs[(2*w+1)*UU + l]
                                          + kbs[(2*w+64)*KBS + l]);
        eo = pv;
        #pragma unroll
        for (int o = 16; o; o >>= 1) eo += __shfl_xor_sync(0xffffffffu, eo, o);
        if (i0 + 2*w + 32 >= LSEQ) eo = -1e30f;   // warp-uniform mask
    }

    // ---- masks ----
    {
        const int j0 = i0 - 32 + c0;              // kA row's key index
        if (j0 < 0){ e0a = -1e30f; e1a = -1e30f; }
        if (j0 + 32 >= LSEQ){ e0b = -1e30f; e1b = -1e30f; }
        if (l == 0) e1a = -1e30f;                 // row 2w not in q1 window
    }

    // ---- two warp softmaxes (q1 includes orphan term) ----
    float a0a, a0b, a1a, a1b, ao;
    {
        float m0 = fmaxf(e0a, e0b), m1 = fmaxf(e1a, e1b);
        #pragma unroll
        for (int o = 16; o; o >>= 1){
            m0 = fmaxf(m0, __shfl_xor_sync(0xffffffffu, m0, o));
            m1 = fmaxf(m1, __shfl_xor_sync(0xffffffffu, m1, o));
        }
        const float M1 = fmaxf(m1, eo);
        const float w0a = __expf(e0a - m0), w0b = __expf(e0b - m0);
        const float w1a = __expf(e1a - M1), w1b = __expf(e1b - M1);
        float s0 = w0a + w0b, s1 = w1a + w1b;
        #pragma unroll
        for (int o = 16; o; o >>= 1){
            s0 += __shfl_xor_sync(0xffffffffu, s0, o);
            s1 += __shfl_xor_sync(0xffffffffu, s1, o);
        }
        const float wo = __expf(eo - M1);         // warp-uniform
        const float inv0 = 1.f / (s0 + 1e-7f);
        const float inv1 = 1.f / ((s1 + wo) + 1e-7f);
        a0a = w0a*inv0; a0b = w0b*inv0;
        a1a = w1a*inv1; a1b = w1b*inv1; ao = wo*inv1;
    }

    // ---- publish: slot k <-> row 2w+k ; (.x=q0, .y=q1) ----
    float* A = Aw + w*132;
    ((float2*)A)[l]      = make_float2(a0a, a1a);   // slots 0..31
    ((float2*)A)[l + 32] = make_float2(a0b, a1b);   // slots 32..63
    if (l == 0) ((float2*)A)[64] = make_float2(0.f, ao);   // orphan slot
    __syncwarp();

    // ---- AV: 4 keys per chunk, 6 batched LDS.128 per 32 FFMA ----
    {
        const float4* xs4 = (const float4*)xs;
        const float4* A4  = (const float4*)A;     // pair j = slots 2j, 2j+1
        float4 acc0 = make_float4(0.f,0.f,0.f,0.f);
        float4 acc1 = make_float4(0.f,0.f,0.f,0.f);
        const int rb = 2*w;
        #pragma unroll
        for (int j = 0; j < 32; j += 2){
            const float4 ab0 = A4[j];                      // batched loads
            const float4 ab1 = A4[j+1];
            const float4 xv0 = xs4[(rb + 2*j    )*32 + l];
            const float4 xv1 = xs4[(rb + 2*j + 1)*32 + l];
            const float4 xv2 = xs4[(rb + 2*j + 2)*32 + l];
            const float4 xv3 = xs4[(rb + 2*j + 3)*32 + l];
            acc0.x += ab0.x*xv0.x; acc0.y += ab0.x*xv0.y;
            acc0.z += ab0.x*xv0.z; acc0.w += ab0.x*xv0.w;
            acc1.x += ab0.y*xv0.x; acc1.y += ab0.y*xv0.y;
            acc1.z += ab0.y*xv0.z; acc1.w += ab0.y*xv0.w;
            acc0.x += ab0.z*xv1.x; acc0.y += ab0.z*xv1.y;
            acc0.z += ab0.z*xv1.z; acc0.w += ab0.z*xv1.w;
            acc1.x += ab0.w*xv1.x; acc1.y += ab0.w*xv1.y;
            acc1.z += ab0.w*xv1.z; acc1.w += ab0.w*xv1.w;
            acc0.x += ab1.x*xv2.x; acc0.y += ab1.x*xv2.y;
            acc0.z += ab1.x*xv2.z; acc0.w += ab1.x*xv2.w;
            acc1.x += ab1.y*xv2.x; acc1.y += ab1.y*xv2.y;
            acc1.z += ab1.y*xv2.z; acc1.w += ab1.y*xv2.w;
            acc0.x += ab1.z*xv3.x; acc0.y += ab1.z*xv3.y;
            acc0.z += ab1.z*xv3.z; acc0.w += ab1.z*xv3.w;
            acc1.x += ab1.w*xv3.x; acc1.y += ab1.w*xv3.y;
            acc1.z += ab1.w*xv3.z; acc1.w += ab1.w*xv3.w;
        }
        {   // orphan key (row 2w+64): q1 only
            const float aov = A[129];                    // slot 64 .y
            const float4 xvo = xs4[(rb + 64)*32 + l];
            acc1.x += aov*xvo.x; acc1.y += aov*xvo.y;
            acc1.z += aov*xvo.z; acc1.w += aov*xvo.w;
        }
        float4* out4 = (float4*)out;
        out4[(base + i0 + rb    )*32 + l] = acc0;
        out4[(base + i0 + rb + 1)*32 + l] = acc1;
    }
}

// ---------------------------------------------------------------------------
extern "C" void kernel_launch(void* const* d_in, const int* in_sizes, int n_in,
                              void* d_out, int out_size)
{
    const float* x  = (const float*)d_in[0];
    const float* Wt = (const float*)d_in[1];
    const float* Wx = (const float*)d_in[2];
    const float* bh = (const float*)d_in[3];
    const float* Wa = (const float*)d_in[4];
    // d_in[5] = ba : cancels exactly in the shifted softmax -> unused
    float* out = (float*)d_out;

    cudaFuncSetAttribute(qk_kernel,
                         cudaFuncAttributeMaxDynamicSharedMemorySize,
                         QK_SMEM_FLOATS*4 + 256);
    qk_kernel<<<NROWS/QK_RPB, 128, QK_SMEM_FLOATS*4>>>(x, Wt, Wx, bh);

    cudaFuncSetAttribute(attn_kernel,
                         cudaFuncAttributeMaxDynamicSharedMemorySize,
                         SMEM_FLOATS*4 + 256);
    dim3 grid(LSEQ/TI, BB);
    attn_kernel<<<grid, 256, SMEM_FLOATS*4>>>(x, Wa, out);
}

// round 12
// speedup vs baseline: 1.1555x; 1.1555x over previous
#include <cuda_runtime.h>

// SeqSelfAttention (Bahdanau additive, windowed) — GB300 sm_103a
// B=4, L=1024, D=128, U=32, WIDTH=64, EPS=1e-7
//
// Algebra: window-max softmax shift only perturbs the +1e-7 denominator by
// exp(Mw-Mfull) (rel err <~1e-6); ba cancels exactly.
// R12: R10 verbatim (best measured: qk=R5-style, attn register-batched,
// lb(256,2)) + PDL overlap: qk triggers launch completion early; attn is
// launched with programmatic stream serialization, stages its x window
// BEFORE cudaGridDependencySynchronize(), then reads g_q/g_kb after the
// sync (= after qk fully completes). Hides attn launch + xs staging
// under qk's mainloop.

#define LSEQ 1024
#define BB   4
#define DD   128
#define UU   32
#define TI   16
#define CW   80   // TI + 64
#define NROWS (BB*LSEQ)

__device__ float g_q [NROWS*UU];
__device__ float g_kb[NROWS*UU];

__device__ __forceinline__ float fast_tanh(float x){
    float y; asm("tanh.approx.f32 %0, %1;" : "=f"(y) : "f"(x)); return y;
}

// ---------------------------------------------------------------------------
// Kernel 1: q = x @ Wt ; kb = x @ Wx + bh.  128 blocks x 256 thr, 32 rows,
// 4 rows/warp. (R5 verbatim — best measured total.)
// ---------------------------------------------------------------------------
#define QK_RPB 32
__global__ __launch_bounds__(256) void qk_kernel(
        const float* __restrict__ x,
        const float* __restrict__ Wt,
        const float* __restrict__ Wx,
        const float* __restrict__ bh)
{
    __shared__ float xs [QK_RPB*DD];    // 16 KB
    __shared__ float wts[DD*UU];        // 16 KB  [d][u]
    __shared__ float wxs[DD*UU];        // 16 KB
    const int t    = threadIdx.x;
    const int row0 = blockIdx.x * QK_RPB;

    {   // stage (all coalesced float4, layout-preserving)
        const float4* xg = (const float4*)(x + row0*DD);
        float4* xs4 = (float4*)xs;
        const float4* wtg = (const float4*)Wt; float4* wt4 = (float4*)wts;
        const float4* wxg = (const float4*)Wx; float4* wx4 = (float4*)wxs;
        #pragma unroll
        for (int i = 0; i < 4; i++){
            xs4[t + i*256] = xg [t + i*256];
            wt4[t + i*256] = wtg[t + i*256];
            wx4[t + i*256] = wxg[t + i*256];
        }
    }
    __syncthreads();

    // Let the dependent attn kernel begin its (qk-independent) prologue.
    cudaTriggerProgrammaticLaunchCompletion();

    const int u  = t & 31;
    const int rg = t >> 5;
    const int rb = rg * 4;                 // 4 rows per warp
    float aq0=0,aq1=0,aq2=0,aq3=0, ak0=0,ak1=0,ak2=0,ak3=0;
    const float4* xs4 = (const float4*)xs;

    #pragma unroll 8
    for (int d4 = 0; d4 < 32; d4++){
        const int db = d4*4*32 + u;
        const float wt0 = wts[db], wt1 = wts[db+32], wt2 = wts[db+64], wt3 = wts[db+96];
        const float wx0 = wxs[db], wx1 = wxs[db+32], wx2 = wxs[db+64], wx3 = wxs[db+96];
        const float4 x0 = xs4[(rb+0)*32 + d4];   // broadcast LDS.128
        const float4 x1 = xs4[(rb+1)*32 + d4];
        const float4 x2 = xs4[(rb+2)*32 + d4];
        const float4 x3 = xs4[(rb+3)*32 + d4];
        aq0 += x0.x*wt0 + x0.y*wt1 + x0.z*wt2 + x0.w*wt3;
        aq1 += x1.x*wt0 + x1.y*wt1 + x1.z*wt2 + x1.w*wt3;
        aq2 += x2.x*wt0 + x2.y*wt1 + x2.z*wt2 + x2.w*wt3;
        aq3 += x3.x*wt0 + x3.y*wt1 + x3.z*wt2 + x3.w*wt3;
        ak0 += x0.x*wx0 + x0.y*wx1 + x0.z*wx2 + x0.w*wx3;
        ak1 += x1.x*wx0 + x1.y*wx1 + x1.z*wx2 + x1.w*wx3;
        ak2 += x2.x*wx0 + x2.y*wx1 + x2.z*wx2 + x2.w*wx3;
        ak3 += x3.x*wx0 + x3.y*wx1 + x3.z*wx2 + x3.w*wx3;
    }
    const float bhv = bh[u];
    const int r = row0 + rb;
    g_q [(r+0)*UU+u] = aq0;      g_q [(r+1)*UU+u] = aq1;
    g_q [(r+2)*UU+u] = aq2;      g_q [(r+3)*UU+u] = aq3;
    g_kb[(r+0)*UU+u] = ak0+bhv;  g_kb[(r+1)*UU+u] = ak1+bhv;
    g_kb[(r+2)*UU+u] = ak2+bhv;  g_kb[(r+3)*UU+u] = ak3+bhv;
}

// ---------------------------------------------------------------------------
// Kernel 2: windowed attention (R10 compute, PDL-split staging).
// grid (L/16, B) = 256 blocks, 256 thr. Warp w owns queries 2w, 2w+1;
// lane l batch-loads kb rows c0=2w+l, c1=c0+32 into registers (MLP 16),
// shared by both queries; q1 orphan row 2w+64 via u-parallel reduction.
// smem: xs[80][128] | kbs[80][36] | qs[16][32] | was[32] | Aw[8][132]
// ---------------------------------------------------------------------------
#define KBS  36
#define OFF_KBS  (CW*DD)                   // 10240
#define OFF_QS   (OFF_KBS + CW*KBS)        // 13120
#define OFF_WAS  (OFF_QS + TI*UU)          // 13632
#define OFF_AW   (OFF_WAS + UU)            // 13664
#define SMEM_FLOATS (OFF_AW + 8*132)       // 14720 floats = 58880 B

extern __shared__ float smem[];

__global__ __launch_bounds__(256, 2) void attn_kernel(
        const float* __restrict__ x,
        const float* __restrict__ Wa,
        float* __restrict__ out)
{
    float* xs  = smem;
    float* kbs = smem + OFF_KBS;
    float* qs  = smem + OFF_QS;
    float* was = smem + OFF_WAS;
    float* Aw  = smem + OFF_AW;

    const int t    = threadIdx.x;
    const int i0   = blockIdx.x * TI;
    const int base = blockIdx.y * LSEQ;

    // ---- phase 1 (qk-independent): stage xs[80][128] f4 and was ----
    {
        float4* xs4 = (float4*)xs;
        const float4* xg4 = (const float4*)x;
        #pragma unroll
        for (int i = 0; i < 10; i++){
            const int idx = t + i*256;            // [0,2560) f4 of [80][32]
            const int c = idx >> 5, dq = idx & 31;
            const int j = i0 - 32 + c;
            float4 v = make_float4(0.f,0.f,0.f,0.f);
            if (j >= 0 && j < LSEQ) v = xg4[(base + j)*32 + dq];
            xs4[c*32 + dq] = v;
        }
        if (t < 32) was[t] = Wa[t];
    }

    // ---- wait for qk_kernel to fully complete (memory visible) ----
    cudaGridDependencySynchronize();

    // ---- phase 2: stage kbs[80][36] f4 and qs[16][32] from qk output ----
    {
        const float4* kg4 = (const float4*)g_kb;
        #pragma unroll
        for (int i = 0; i < 3; i++){
            const int idx = t + i*256;            // [0,640) f4 of [80][8]
            if (idx < 640){
                const int c = idx >> 3, u4 = idx & 7;
                const int j = i0 - 32 + c;
                float4 v = make_float4(0.f,0.f,0.f,0.f);
                if (j >= 0 && j < LSEQ) v = kg4[(base + j)*8 + u4];
                ((float4*)(kbs + c*KBS))[u4] = v;
            }
        }
        if (t < 128) ((float4*)qs)[t] = ((const float4*)(g_q + (base+i0)*UU))[t];
    }
    __syncthreads();

    const int w = t >> 5;
    const int l = t & 31;
    const int c0 = 2*w + l, c1 = c0 + 32;

    // ---- batch-load the lane's full kb working set (16 indep LDS.128) ----
    float4 kA[8], kB[8];
    {
        const float4* kAp = (const float4*)(kbs + c0*KBS);
        const float4* kBp = (const float4*)(kbs + c1*KBS);
        #pragma unroll
        for (int u4 = 0; u4 < 8; u4++) kA[u4] = kAp[u4];
        #pragma unroll
        for (int u4 = 0; u4 < 8; u4++) kB[u4] = kBp[u4];
    }

    // ---- logits: kA/kB in registers, shared by q0 and q1 ----
    float e0a = 0.f, e0b = 0.f, e1a = 0.f, e1b = 0.f;
    {
        const float4* q0p = (const float4*)(qs + 2*w*UU);
        const float4* q1p = q0p + 8;
        const float4* wap = (const float4*)was;
        #pragma unroll
        for (int u4 = 0; u4 < 8; u4++){
            const float4 wa = wap[u4];            // broadcast
            const float4 q0 = q0p[u4];            // broadcast
            const float4 q1 = q1p[u4];
            e0a += wa.x*fast_tanh(q0.x+kA[u4].x) + wa.y*fast_tanh(q0.y+kA[u4].y)
                 + wa.z*fast_tanh(q0.z+kA[u4].z) + wa.w*fast_tanh(q0.w+kA[u4].w);
            e0b += wa.x*fast_tanh(q0.x+kB[u4].x) + wa.y*fast_tanh(q0.y+kB[u4].y)
                 + wa.z*fast_tanh(q0.z+kB[u4].z) + wa.w*fast_tanh(q0.w+kB[u4].w);
            e1a += wa.x*fast_tanh(q1.x+kA[u4].x) + wa.y*fast_tanh(q1.y+kA[u4].y)
                 + wa.z*fast_tanh(q1.z+kA[u4].z) + wa.w*fast_tanh(q1.w+kA[u4].w);
            e1b += wa.x*fast_tanh(q1.x+kB[u4].x) + wa.y*fast_tanh(q1.y+kB[u4].y)
                 + wa.z*fast_tanh(q1.z+kB[u4].z) + wa.w*fast_tanh(q1.w+kB[u4].w);
        }
    }

    // ---- orphan row 2w+64 for q1: u-parallel (lane = unit) ----
    float eo;
    {
        const float pv = was[l] * fast_tanh(qs[(2*w+1)*UU + l]
                                          + kbs[(2*w+64)*KBS + l]);
        eo = pv;
        #pragma unroll
        for (int o = 16; o; o >>= 1) eo += __shfl_xor_sync(0xffffffffu, eo, o);
        if (i0 + 2*w + 32 >= LSEQ) eo = -1e30f;   // warp-uniform mask
    }

    // ---- masks ----
    {
        const int j0 = i0 - 32 + c0;              // kA row's key index
        if (j0 < 0){ e0a = -1e30f; e1a = -1e30f; }
        if (j0 + 32 >= LSEQ){ e0b = -1e30f; e1b = -1e30f; }
        if (l == 0) e1a = -1e30f;                 // row 2w not in q1 window
    }

    // ---- two warp softmaxes (q1 includes orphan term) ----
    float a0a, a0b, a1a, a1b, ao;
    {
        float m0 = fmaxf(e0a, e0b), m1 = fmaxf(e1a, e1b);
        #pragma unroll
        for (int o = 16; o; o >>= 1){
            m0 = fmaxf(m0, __shfl_xor_sync(0xffffffffu, m0, o));
            m1 = fmaxf(m1, __shfl_xor_sync(0xffffffffu, m1, o));
        }
        const float M1 = fmaxf(m1, eo);
        const float w0a = __expf(e0a - m0), w0b = __expf(e0b - m0);
        const float w1a = __expf(e1a - M1), w1b = __expf(e1b - M1);
        float s0 = w0a + w0b, s1 = w1a + w1b;
        #pragma unroll
        for (int o = 16; o; o >>= 1){
            s0 += __shfl_xor_sync(0xffffffffu, s0, o);
            s1 += __shfl_xor_sync(0xffffffffu, s1, o);
        }
        const float wo = __expf(eo - M1);         // warp-uniform
        const float inv0 = 1.f / (s0 + 1e-7f);
        const float inv1 = 1.f / ((s1 + wo) + 1e-7f);
        a0a = w0a*inv0; a0b = w0b*inv0;
        a1a = w1a*inv1; a1b = w1b*inv1; ao = wo*inv1;
    }

    // ---- publish: slot k <-> row 2w+k ; (.x=q0, .y=q1) ----
    float* A = Aw + w*132;
    ((float2*)A)[l]      = make_float2(a0a, a1a);   // slots 0..31
    ((float2*)A)[l + 32] = make_float2(a0b, a1b);   // slots 32..63
    if (l == 0) ((float2*)A)[64] = make_float2(0.f, ao);   // orphan slot
    __syncwarp();

    // ---- AV: 4 keys per chunk, 6 batched LDS.128 per 32 FFMA ----
    {
        const float4* xs4 = (const float4*)xs;
        const float4* A4  = (const float4*)A;     // pair j = slots 2j, 2j+1
        float4 acc0 = make_float4(0.f,0.f,0.f,0.f);
        float4 acc1 = make_float4(0.f,0.f,0.f,0.f);
        const int rb = 2*w;
        #pragma unroll
        for (int j = 0; j < 32; j += 2){
            const float4 ab0 = A4[j];                      // batched loads
            const float4 ab1 = A4[j+1];
            const float4 xv0 = xs4[(rb + 2*j    )*32 + l];
            const float4 xv1 = xs4[(rb + 2*j + 1)*32 + l];
            const float4 xv2 = xs4[(rb + 2*j + 2)*32 + l];
            const float4 xv3 = xs4[(rb + 2*j + 3)*32 + l];
            acc0.x += ab0.x*xv0.x; acc0.y += ab0.x*xv0.y;
            acc0.z += ab0.x*xv0.z; acc0.w += ab0.x*xv0.w;
            acc1.x += ab0.y*xv0.x; acc1.y += ab0.y*xv0.y;
            acc1.z += ab0.y*xv0.z; acc1.w += ab0.y*xv0.w;
            acc0.x += ab0.z*xv1.x; acc0.y += ab0.z*xv1.y;
            acc0.z += ab0.z*xv1.z; acc0.w += ab0.z*xv1.w;
            acc1.x += ab0.w*xv1.x; acc1.y += ab0.w*xv1.y;
            acc1.z += ab0.w*xv1.z; acc1.w += ab0.w*xv1.w;
            acc0.x += ab1.x*xv2.x; acc0.y += ab1.x*xv2.y;
            acc0.z += ab1.x*xv2.z; acc0.w += ab1.x*xv2.w;
            acc1.x += ab1.y*xv2.x; acc1.y += ab1.y*xv2.y;
            acc1.z += ab1.y*xv2.z; acc1.w += ab1.y*xv2.w;
            acc0.x += ab1.z*xv3.x; acc0.y += ab1.z*xv3.y;
            acc0.z += ab1.z*xv3.z; acc0.w += ab1.z*xv3.w;
            acc1.x += ab1.w*xv3.x; acc1.y += ab1.w*xv3.y;
            acc1.z += ab1.w*xv3.z; acc1.w += ab1.w*xv3.w;
        }
        {   // orphan key (row 2w+64): q1 only
            const float aov = A[129];                    // slot 64 .y
            const float4 xvo = xs4[(rb + 64)*32 + l];
            acc1.x += aov*xvo.x; acc1.y += aov*xvo.y;
            acc1.z += aov*xvo.z; acc1.w += aov*xvo.w;
        }
        float4* out4 = (float4*)out;
        out4[(base + i0 + rb    )*32 + l] = acc0;
        out4[(base + i0 + rb + 1)*32 + l] = acc1;
    }
}

// ---------------------------------------------------------------------------
extern "C" void kernel_launch(void* const* d_in, const int* in_sizes, int n_in,
                              void* d_out, int out_size)
{
    const float* x  = (const float*)d_in[0];
    const float* Wt = (const float*)d_in[1];
    const float* Wx = (const float*)d_in[2];
    const float* bh = (const float*)d_in[3];
    const float* Wa = (const float*)d_in[4];
    // d_in[5] = ba : cancels exactly in the shifted softmax -> unused
    float* out = (float*)d_out;

    qk_kernel<<<NROWS/QK_RPB, 256>>>(x, Wt, Wx, bh);

    cudaFuncSetAttribute(attn_kernel,
                         cudaFuncAttributeMaxDynamicSharedMemorySize,
                         SMEM_FLOATS*4 + 256);

    // PDL launch: attn may start its prologue while qk runs; the
    // cudaGridDependencySynchronize() inside orders the g_q/g_kb reads.
    cudaLaunchConfig_t cfg = {};
    cfg.gridDim  = dim3(LSEQ/TI, BB, 1);
    cfg.blockDim = dim3(256, 1, 1);
    cfg.dynamicSmemBytes = SMEM_FLOATS*4;
    cfg.stream = 0;
    cudaLaunchAttribute at[1];
    at[0].id = cudaLaunchAttributeProgrammaticStreamSerialization;
    at[0].val.programmaticStreamSerializationAllowed = 1;
    cfg.attrs = at;
    cfg.numAttrs = 1;
    cudaLaunchKernelEx(&cfg, attn_kernel, x, Wa, out);
}